// round 9
// baseline (speedup 1.0000x reference)
#include <cuda_runtime.h>
#include <math.h>

#define N    2048
#define HID  16
#define TPB  256
#define T    32
#define NT   (N / T)               // 64
#define NBLK (NT * (NT + 1) / 2)   // 2080

// Per-signal derived scalars: [i*2+0]={t,ra,dec,mc}  [i*2+1]={f_isco,dist,psi,0}
__device__ float4 g_pre4[2 * N];
// Accumulators per row: {sum_e, sum_e*f0 .. sum_e*f7}
__device__ float g_acc[N * 9];
// Preprocessed importance-net weights (W1c = W1 - colmean, b1c = b1 - mean(b1)):
// g_wA[h]=W1c[h][0..3], g_wB[h]=W1c[h][4..7], g_pp[h]={g1, bt1, 0.5*w2, b1c}
__device__ float4 g_wA[HID], g_wB[HID], g_pp[HID];
__device__ float g_w2g[HID];   // w2*g1 (folded linear dot)
__device__ float g_cL[1];      // sum_h w2*bt1

__device__ __forceinline__ float rcpa(float x) {
    float r; asm("rcp.approx.f32 %0, %1;" : "=f"(r) : "f"(x)); return r;
}
__device__ __forceinline__ float ex2a(float x) {
    float r; asm("ex2.approx.f32 %0, %1;" : "=f"(r) : "f"(x)); return r;
}
__device__ __forceinline__ float lg2a(float x) {
    float r; asm("lg2.approx.f32 %0, %1;" : "=f"(r) : "f"(x)); return r;
}

// ---------------------------------------------------------------------------
// Pre: per-signal scalars (blocks 0-63), weight prep (block 64), acc zeroing.
// ---------------------------------------------------------------------------
__global__ void pre_kernel(const float* __restrict__ p,
                           const float* __restrict__ iw1, const float* __restrict__ ib1,
                           const float* __restrict__ ig1, const float* __restrict__ ibt1,
                           const float* __restrict__ iw2)
{
    int tid = threadIdx.x;
    int b   = blockIdx.x;
    if (b < 64) {
        int i = b * 32 + tid;
        const float* pi = p + i * 15;
        float m1 = fmaf(pi[0], 95.f, 5.f);
        float m2 = fmaf(pi[1], 95.f, 5.f);
        float mc = ex2a(fmaf(0.6f, lg2a(m1 * m2), -0.2f * lg2a(m1 + m2)));
        g_pre4[i * 2 + 0] = make_float4(pi[5], pi[3], pi[4], mc);
        g_pre4[i * 2 + 1] = make_float4(220.f / (m1 + m2), fmaf(pi[2], 2950.f, 50.f), pi[7], 0.f);
        float* za = g_acc + (size_t)i * 9;
#pragma unroll
        for (int k = 0; k < 9; k++) za[k] = 0.f;
    } else {
        __shared__ float s_col[8];
        __shared__ float s_bm;
        if (tid < 8) {
            float s = 0.f;
#pragma unroll
            for (int h = 0; h < HID; h++) s += iw1[h * 8 + tid];
            s_col[tid] = s * (1.f / HID);
        }
        if (tid == 0) {
            float bm = 0.f, cl = 0.f;
#pragma unroll
            for (int h = 0; h < HID; h++) { bm += ib1[h]; cl += iw2[h] * ibt1[h]; }
            s_bm = bm * (1.f / HID);
            g_cL[0] = cl;
        }
        __syncthreads();
        if (tid < HID) {
            int h = tid;
            g_wA[h] = make_float4(iw1[h*8+0] - s_col[0], iw1[h*8+1] - s_col[1],
                                  iw1[h*8+2] - s_col[2], iw1[h*8+3] - s_col[3]);
            g_wB[h] = make_float4(iw1[h*8+4] - s_col[4], iw1[h*8+5] - s_col[5],
                                  iw1[h*8+6] - s_col[6], iw1[h*8+7] - s_col[7]);
            g_pp[h] = make_float4(ig1[h], ibt1[h], 0.5f * iw2[h], ib1[h] - s_bm);
            g_w2g[h] = iw2[h] * ig1[h];
        }
    }
}

// ---------------------------------------------------------------------------
// Pair kernel: 32x32 tiles, triangular grid. Computes e=exp(logit) per pair,
// accumulates {e, e*f0..e*f7} into BOTH row-i and row-j accumulators.
// ---------------------------------------------------------------------------
__global__ __launch_bounds__(TPB) void pair_kernel(const float* __restrict__ ib2)
{
    __shared__ float4 s_wA[HID], s_wB[HID], s_pp[HID];
    __shared__ float  s_w2g[HID];
    __shared__ float  s_ipre[7][T];
    __shared__ float  s_jred[8][T][9];

    const int tid  = threadIdx.x;
    const int lane = tid & 31;
    const int wg   = tid >> 5;

    // Triangular decode: blocks enumerate (ti, tj) with tj >= ti.
    int b = blockIdx.x;
    int ti = (int)((2.f * NT + 1.f - sqrtf((2.f * NT + 1.f) * (2.f * NT + 1.f) - 8.f * (float)b)) * 0.5f);
    if (ti >= NT) ti = NT - 1;
    while (ti > 0 && (ti * NT - ti * (ti - 1) / 2) > b) ti--;
    while (((ti + 1) * NT - (ti + 1) * ti / 2) <= b) ti++;
    const int tj = ti + (b - (ti * NT - ti * (ti - 1) / 2));
    const bool diag = (ti == tj);

    if (tid < HID)            s_wA[tid]        = g_wA[tid];
    else if (tid < 2*HID)     s_wB[tid-HID]    = g_wB[tid-HID];
    else if (tid < 3*HID)     s_pp[tid-2*HID]  = g_pp[tid-2*HID];
    else if (tid < 4*HID)     s_w2g[tid-3*HID] = g_w2g[tid-3*HID];
    else if (tid >= 128 && tid < 160) {
        int r = tid - 128;
        int ii = ti * T + r;
        float4 a = g_pre4[ii * 2 + 0];
        float4 c = g_pre4[ii * 2 + 1];
        s_ipre[0][r] = a.x; s_ipre[1][r] = a.y; s_ipre[2][r] = a.z;
        s_ipre[3][r] = a.w; s_ipre[4][r] = c.x; s_ipre[5][r] = c.y;
        s_ipre[6][r] = c.z;
    }

    const float lg0 = ib2[0] + 0.5f * g_cL[0];

    // j-side scalars in registers for the whole block
    const int j = tj * T + lane;
    const float4 ja = g_pre4[j * 2 + 0];
    const float4 jb = g_pre4[j * 2 + 1];
    const float tj_ = ja.x, raj = ja.y, dej = ja.z, mcj = ja.w;
    const float fij = jb.x, dij = jb.y, psj = jb.z;

    float jacc[9];
#pragma unroll
    for (int k = 0; k < 9; k++) jacc[k] = 0.f;

    __syncthreads();

#pragma unroll
    for (int m = 0; m < 4; m++) {
        const int r = (m << 3) + wg;
        const int i = ti * T + r;
        float v[9];
        const bool valid = (!diag) || (j > i);
        if (valid) {
            const float ti_ = s_ipre[0][r], rai = s_ipre[1][r], dei = s_ipre[2][r];
            const float mci = s_ipre[3][r], fii = s_ipre[4][r], dii = s_ipre[5][r];
            const float psi = s_ipre[6][r];

            float dra = fabsf(rai - raj);
            float dde = fabsf(dei - dej);
            float f0 = fabsf(ti_ - tj_);
            float ss = fmaxf(fmaf(dra, dra, dde * dde), 1e-30f);
            float f1 = ss * rsqrtf(ss);
            float f2 = rcpa(fmaf(fabsf(mci - mcj), (1.f / 30.f), 1.f));
            float f3 = ex2a(-fabsf(fii - fij) * 0.0144269504f);
            float f4 = fminf(dii, dij) * rcpa(fmaxf(dii, dij));
            float f5 = fabsf(psi - psj);

            float zc[HID];
            float var = 0.f, dot = 0.f;
#pragma unroll
            for (int h = 0; h < HID; h++) {
                float4 wa = s_wA[h];
                float4 wb = s_wB[h];
                float a = s_pp[h].w;               // b1c
                a = fmaf(wa.x, f0, a); a = fmaf(wa.y, f1, a);
                a = fmaf(wa.z, f2, a); a = fmaf(wa.w, f3, a);
                a = fmaf(wb.x, f4, a); a = fmaf(wb.y, f5, a);
                a = fmaf(wb.z, dra, a); a = fmaf(wb.w, dde, a);
                zc[h] = a;
                var = fmaf(a, a, var);
                dot = fmaf(s_w2g[h], a, dot);
            }
            float inv = rsqrtf(fmaf(var, (1.f / HID), 1e-5f));
            float lg = fmaf(0.5f * inv, dot, lg0);
            // erf epilogue: A&S 7.1.25 (3-term, |err| <= 2.5e-5)
#pragma unroll
            for (int h = 0; h < HID; h++) {
                float4 pp = s_pp[h];
                float xn = fmaf(zc[h] * inv, pp.x, pp.y);
                float ax = fabsf(xn) * 0.70710678118654752f;
                float u  = rcpa(fmaf(0.47047f, ax, 1.f));
                float pl = fmaf(fmaf(0.7478556f, u, -0.0958798f), u, 0.3480242f) * u;
                float e_ = ex2a(-0.72134752044448f * (xn * xn));   // e^{-ax^2}
                float er = fmaf(-pl, e_, 1.f);
                er = copysignf(er, xn);
                lg = fmaf(pp.z * xn, er, lg);     // 0.5*w2*xn*erf
            }
            float e = ex2a(lg * 1.44269504088896f);

            v[0] = e;
            v[1] = e * f0; v[2] = e * f1; v[3] = e * f2; v[4] = e * f3;
            v[5] = e * f4; v[6] = e * f5; v[7] = e * dra; v[8] = e * dde;
#pragma unroll
            for (int k = 0; k < 9; k++) jacc[k] += v[k];
        } else {
#pragma unroll
            for (int k = 0; k < 9; k++) v[k] = 0.f;
        }
        // Row-side: 2-step butterfly -> 8 disjoint group sums in lanes 0-7,
        // each lane adds its group partial (L2 REDG accumulates the rest).
#pragma unroll
        for (int k = 0; k < 9; k++) {
            float x = v[k];
            x += __shfl_xor_sync(0xFFFFFFFFu, x, 16);
            x += __shfl_xor_sync(0xFFFFFFFFu, x, 8);
            if (lane < 8) atomicAdd(&g_acc[(size_t)i * 9 + k], x);
        }
    }

    // Col-side: per-thread register acc -> smem -> 32-thread reduce + atomics
#pragma unroll
    for (int k = 0; k < 9; k++) s_jred[wg][lane][k] = jacc[k];
    __syncthreads();
    if (tid < 32) {
        const int jj = tj * T + tid;
#pragma unroll
        for (int k = 0; k < 9; k++) {
            float s = 0.f;
#pragma unroll
            for (int w = 0; w < 8; w++) s += s_jred[w][tid][k];
            atomicAdd(&g_acc[(size_t)jj * 9 + k], s);
        }
    }
}

// ---------------------------------------------------------------------------
// Final: normalize + overlap net. One warp per row.
// ---------------------------------------------------------------------------
__global__ __launch_bounds__(TPB) void final_kernel(
    const float* __restrict__ ow1, const float* __restrict__ ob1,
    const float* __restrict__ og1, const float* __restrict__ obt1,
    const float* __restrict__ ow2, const float* __restrict__ ob2,
    float* __restrict__ out)
{
    __shared__ float s_h2[8][32];
    const int tid  = threadIdx.x;
    const int lane = tid & 31;
    const int wid  = tid >> 5;
    const int row  = blockIdx.x * 8 + wid;

    float myv = (lane < 9) ? g_acc[(size_t)row * 9 + lane] : 0.f;
    float invS = rcpa(__shfl_sync(0xFFFFFFFFu, myv, 0));

    float a = ob1[lane];
#pragma unroll
    for (int f = 0; f < 8; f++)
        a = fmaf(ow1[lane * 8 + f], __shfl_sync(0xFFFFFFFFu, myv, f + 1) * invS, a);

    float s = a;
#pragma unroll
    for (int o = 16; o; o >>= 1) s += __shfl_xor_sync(0xFFFFFFFFu, s, o);
    float mu = s * (1.f / 32.f);
    float d = a - mu;
    float v = d * d;
#pragma unroll
    for (int o = 16; o; o >>= 1) v += __shfl_xor_sync(0xFFFFFFFFu, v, o);
    float invs = rsqrtf(fmaf(v, (1.f / 32.f), 1e-5f));
    float xn = fmaf(d * invs, og1[lane], obt1[lane]);

    // accurate 4-term erf (only 32 lanes per row — cost irrelevant)
    float ax = fabsf(xn) * 0.70710678118654752f;
    float u  = rcpa(fmaf(0.3275911f, ax, 1.f));
    float pl = fmaf(fmaf(fmaf(fmaf(1.061405429f, u, -1.453152027f),
                               u, 1.421413741f),
                          u, -0.284496736f),
                     u, 0.254829592f) * u;
    float e_ = ex2a(-1.44269504088896f * (ax * ax));
    float er = fmaf(-pl, e_, 1.f);
    er = copysignf(er, xn);
    s_h2[wid][lane] = 0.5f * xn * (1.f + er);
    __syncwarp();

    if (lane < 16) {
        float o_ = ob2[lane];
#pragma unroll
        for (int k = 0; k < 32; k++) o_ = fmaf(ow2[lane * 32 + k], s_h2[wid][k], o_);
        out[row * 16 + lane] = o_;
    }
}

extern "C" void kernel_launch(void* const* d_in, const int* in_sizes, int n_in,
                              void* d_out, int out_size) {
    const float* params = (const float*)d_in[0];
    const float* iw1  = (const float*)d_in[1];
    const float* ib1  = (const float*)d_in[2];
    const float* ig1  = (const float*)d_in[3];
    const float* ibt1 = (const float*)d_in[4];
    const float* iw2  = (const float*)d_in[5];
    const float* ib2  = (const float*)d_in[6];
    const float* ow1  = (const float*)d_in[7];
    const float* ob1  = (const float*)d_in[8];
    const float* og1  = (const float*)d_in[9];
    const float* obt1 = (const float*)d_in[10];
    const float* ow2  = (const float*)d_in[11];
    const float* ob2  = (const float*)d_in[12];
    float* out = (float*)d_out;

    pre_kernel<<<65, 32>>>(params, iw1, ib1, ig1, ibt1, iw2);
    pair_kernel<<<NBLK, TPB>>>(ib2);
    final_kernel<<<N / 8, TPB>>>(ow1, ob1, og1, obt1, ow2, ob2, out);
}

// round 10
// speedup vs baseline: 2.6191x; 2.6191x over previous
#include <cuda_runtime.h>
#include <math.h>

#define N    2048
#define HID  16
#define TPB  256
#define T    32
#define NT   (N / T)               // 64
#define NBLK (NT * (NT + 1) / 2)   // 2080

// Per-signal derived scalars: [i*2+0]={t,ra,dec,mc}  [i*2+1]={f_isco,dist,psi,0}
__device__ float4 g_pre4[2 * N];
// Accumulators per row: {sum_e, sum_e*f0 .. sum_e*f7}
__device__ float g_acc[N * 9];
// Preprocessed importance-net weights (W1c = W1 - colmean, b1c = b1 - mean(b1)):
// g_wA[h]=W1c[h][0..3], g_wB[h]=W1c[h][4..7], g_pp[h]={g1, bt1, 0.5*w2, b1c}
__device__ float4 g_wA[HID], g_wB[HID], g_pp[HID];
__device__ float g_w2g[HID];   // w2*g1 (folded linear dot)
__device__ float g_cL[1];      // sum_h w2*bt1

__device__ __forceinline__ float rcpa(float x) {
    float r; asm("rcp.approx.f32 %0, %1;" : "=f"(r) : "f"(x)); return r;
}
__device__ __forceinline__ float ex2a(float x) {
    float r; asm("ex2.approx.f32 %0, %1;" : "=f"(r) : "f"(x)); return r;
}
__device__ __forceinline__ float lg2a(float x) {
    float r; asm("lg2.approx.f32 %0, %1;" : "=f"(r) : "f"(x)); return r;
}

// ---------------------------------------------------------------------------
// Pre: per-signal scalars (blocks 0-63), weight prep (block 64), acc zeroing.
// ---------------------------------------------------------------------------
__global__ void pre_kernel(const float* __restrict__ p,
                           const float* __restrict__ iw1, const float* __restrict__ ib1,
                           const float* __restrict__ ig1, const float* __restrict__ ibt1,
                           const float* __restrict__ iw2)
{
    int tid = threadIdx.x;
    int b   = blockIdx.x;
    if (b < 64) {
        int i = b * 32 + tid;
        const float* pi = p + i * 15;
        float m1 = fmaf(pi[0], 95.f, 5.f);
        float m2 = fmaf(pi[1], 95.f, 5.f);
        float mc = ex2a(fmaf(0.6f, lg2a(m1 * m2), -0.2f * lg2a(m1 + m2)));
        g_pre4[i * 2 + 0] = make_float4(pi[5], pi[3], pi[4], mc);
        g_pre4[i * 2 + 1] = make_float4(220.f / (m1 + m2), fmaf(pi[2], 2950.f, 50.f), pi[7], 0.f);
        float* za = g_acc + (size_t)i * 9;
#pragma unroll
        for (int k = 0; k < 9; k++) za[k] = 0.f;
    } else {
        __shared__ float s_col[8];
        __shared__ float s_bm;
        if (tid < 8) {
            float s = 0.f;
#pragma unroll
            for (int h = 0; h < HID; h++) s += iw1[h * 8 + tid];
            s_col[tid] = s * (1.f / HID);
        }
        if (tid == 0) {
            float bm = 0.f, cl = 0.f;
#pragma unroll
            for (int h = 0; h < HID; h++) { bm += ib1[h]; cl += iw2[h] * ibt1[h]; }
            s_bm = bm * (1.f / HID);
            g_cL[0] = cl;
        }
        __syncthreads();
        if (tid < HID) {
            int h = tid;
            g_wA[h] = make_float4(iw1[h*8+0] - s_col[0], iw1[h*8+1] - s_col[1],
                                  iw1[h*8+2] - s_col[2], iw1[h*8+3] - s_col[3]);
            g_wB[h] = make_float4(iw1[h*8+4] - s_col[4], iw1[h*8+5] - s_col[5],
                                  iw1[h*8+6] - s_col[6], iw1[h*8+7] - s_col[7]);
            g_pp[h] = make_float4(ig1[h], ibt1[h], 0.5f * iw2[h], ib1[h] - s_bm);
            g_w2g[h] = iw2[h] * ig1[h];
        }
    }
}

// ---------------------------------------------------------------------------
// Pair kernel: 32x32 tiles, triangular grid. Computes e=exp(logit) per pair,
// accumulates {e, e*f0..e*f7} into BOTH row-i and row-j accumulators.
// ---------------------------------------------------------------------------
__global__ __launch_bounds__(TPB) void pair_kernel(const float* __restrict__ ib2)
{
    __shared__ float4 s_wA[HID], s_wB[HID], s_pp[HID];
    __shared__ float  s_w2g[HID];
    __shared__ float  s_ipre[7][T];
    __shared__ float  s_jred[8][T][9];

    const int tid  = threadIdx.x;
    const int lane = tid & 31;
    const int wg   = tid >> 5;

    // Triangular decode: blocks enumerate (ti, tj) with tj >= ti.
    int b = blockIdx.x;
    int ti = (int)((2.f * NT + 1.f - sqrtf((2.f * NT + 1.f) * (2.f * NT + 1.f) - 8.f * (float)b)) * 0.5f);
    if (ti >= NT) ti = NT - 1;
    while (ti > 0 && (ti * NT - ti * (ti - 1) / 2) > b) ti--;
    while (((ti + 1) * NT - (ti + 1) * ti / 2) <= b) ti++;
    const int tj = ti + (b - (ti * NT - ti * (ti - 1) / 2));
    const bool diag = (ti == tj);

    if (tid < HID)            s_wA[tid]        = g_wA[tid];
    else if (tid < 2*HID)     s_wB[tid-HID]    = g_wB[tid-HID];
    else if (tid < 3*HID)     s_pp[tid-2*HID]  = g_pp[tid-2*HID];
    else if (tid < 4*HID)     s_w2g[tid-3*HID] = g_w2g[tid-3*HID];
    else if (tid >= 128 && tid < 160) {
        int r = tid - 128;
        int ii = ti * T + r;
        float4 a = g_pre4[ii * 2 + 0];
        float4 c = g_pre4[ii * 2 + 1];
        s_ipre[0][r] = a.x; s_ipre[1][r] = a.y; s_ipre[2][r] = a.z;
        s_ipre[3][r] = a.w; s_ipre[4][r] = c.x; s_ipre[5][r] = c.y;
        s_ipre[6][r] = c.z;
    }

    const float lg0 = ib2[0] + 0.5f * g_cL[0];

    // j-side scalars in registers for the whole block
    const int j = tj * T + lane;
    const float4 ja = g_pre4[j * 2 + 0];
    const float4 jb = g_pre4[j * 2 + 1];
    const float tj_ = ja.x, raj = ja.y, dej = ja.z, mcj = ja.w;
    const float fij = jb.x, dij = jb.y, psj = jb.z;

    float jacc[9];
#pragma unroll
    for (int k = 0; k < 9; k++) jacc[k] = 0.f;

    __syncthreads();

#pragma unroll
    for (int m = 0; m < 4; m++) {
        const int r = (m << 3) + wg;
        const int i = ti * T + r;
        float v[9];
        const bool valid = (!diag) || (j > i);
        if (valid) {
            const float ti_ = s_ipre[0][r], rai = s_ipre[1][r], dei = s_ipre[2][r];
            const float mci = s_ipre[3][r], fii = s_ipre[4][r], dii = s_ipre[5][r];
            const float psi = s_ipre[6][r];

            float dra = fabsf(rai - raj);
            float dde = fabsf(dei - dej);
            float f0 = fabsf(ti_ - tj_);
            float ss = fmaxf(fmaf(dra, dra, dde * dde), 1e-30f);
            float f1 = ss * rsqrtf(ss);
            float f2 = rcpa(fmaf(fabsf(mci - mcj), (1.f / 30.f), 1.f));
            float f3 = ex2a(-fabsf(fii - fij) * 0.0144269504f);
            float f4 = fminf(dii, dij) * rcpa(fmaxf(dii, dij));
            float f5 = fabsf(psi - psj);

            float zc[HID];
            float var = 0.f, dot = 0.f;
#pragma unroll
            for (int h = 0; h < HID; h++) {
                float4 wa = s_wA[h];
                float4 wb = s_wB[h];
                float a = s_pp[h].w;               // b1c
                a = fmaf(wa.x, f0, a); a = fmaf(wa.y, f1, a);
                a = fmaf(wa.z, f2, a); a = fmaf(wa.w, f3, a);
                a = fmaf(wb.x, f4, a); a = fmaf(wb.y, f5, a);
                a = fmaf(wb.z, dra, a); a = fmaf(wb.w, dde, a);
                zc[h] = a;
                var = fmaf(a, a, var);
                dot = fmaf(s_w2g[h], a, dot);
            }
            float inv = rsqrtf(fmaf(var, (1.f / HID), 1e-5f));
            float lg = fmaf(0.5f * inv, dot, lg0);
            // erf epilogue: A&S 7.1.25 (3-term) — validated rel_err ~6.7e-7 in R9
#pragma unroll
            for (int h = 0; h < HID; h++) {
                float4 pp = s_pp[h];
                float xn = fmaf(zc[h] * inv, pp.x, pp.y);
                float ax = fabsf(xn) * 0.70710678118654752f;
                float u  = rcpa(fmaf(0.47047f, ax, 1.f));
                float pl = fmaf(fmaf(0.7478556f, u, -0.0958798f), u, 0.3480242f) * u;
                float e_ = ex2a(-0.72134752044448f * (xn * xn));   // e^{-ax^2}
                float er = fmaf(-pl, e_, 1.f);
                er = copysignf(er, xn);
                lg = fmaf(pp.z * xn, er, lg);     // 0.5*w2*xn*erf
            }
            float e = ex2a(lg * 1.44269504088896f);

            v[0] = e;
            v[1] = e * f0; v[2] = e * f1; v[3] = e * f2; v[4] = e * f3;
            v[5] = e * f4; v[6] = e * f5; v[7] = e * dra; v[8] = e * dde;
#pragma unroll
            for (int k = 0; k < 9; k++) jacc[k] += v[k];
        } else {
#pragma unroll
            for (int k = 0; k < 9; k++) v[k] = 0.f;
        }
        // Row-side: full warp shfl reduce, ONE atomic per (i,k) from lane 0.
#pragma unroll
        for (int k = 0; k < 9; k++) {
            float x = v[k];
#pragma unroll
            for (int o = 16; o; o >>= 1) x += __shfl_xor_sync(0xFFFFFFFFu, x, o);
            if (lane == 0) atomicAdd(&g_acc[(size_t)i * 9 + k], x);
        }
    }

    // Col-side: per-thread register acc -> smem -> 32-thread reduce + atomics
#pragma unroll
    for (int k = 0; k < 9; k++) s_jred[wg][lane][k] = jacc[k];
    __syncthreads();
    if (tid < 32) {
        const int jj = tj * T + tid;
#pragma unroll
        for (int k = 0; k < 9; k++) {
            float s = 0.f;
#pragma unroll
            for (int w = 0; w < 8; w++) s += s_jred[w][tid][k];
            atomicAdd(&g_acc[(size_t)jj * 9 + k], s);
        }
    }
}

// ---------------------------------------------------------------------------
// Final: normalize + overlap net. One warp per row.
// ---------------------------------------------------------------------------
__global__ __launch_bounds__(TPB) void final_kernel(
    const float* __restrict__ ow1, const float* __restrict__ ob1,
    const float* __restrict__ og1, const float* __restrict__ obt1,
    const float* __restrict__ ow2, const float* __restrict__ ob2,
    float* __restrict__ out)
{
    __shared__ float s_h2[8][32];
    const int tid  = threadIdx.x;
    const int lane = tid & 31;
    const int wid  = tid >> 5;
    const int row  = blockIdx.x * 8 + wid;

    float myv = (lane < 9) ? g_acc[(size_t)row * 9 + lane] : 0.f;
    float invS = rcpa(__shfl_sync(0xFFFFFFFFu, myv, 0));

    float a = ob1[lane];
#pragma unroll
    for (int f = 0; f < 8; f++)
        a = fmaf(ow1[lane * 8 + f], __shfl_sync(0xFFFFFFFFu, myv, f + 1) * invS, a);

    float s = a;
#pragma unroll
    for (int o = 16; o; o >>= 1) s += __shfl_xor_sync(0xFFFFFFFFu, s, o);
    float mu = s * (1.f / 32.f);
    float d = a - mu;
    float v = d * d;
#pragma unroll
    for (int o = 16; o; o >>= 1) v += __shfl_xor_sync(0xFFFFFFFFu, v, o);
    float invs = rsqrtf(fmaf(v, (1.f / 32.f), 1e-5f));
    float xn = fmaf(d * invs, og1[lane], obt1[lane]);

    // accurate 4-term erf (only 32 lanes per row — cost irrelevant)
    float ax = fabsf(xn) * 0.70710678118654752f;
    float u  = rcpa(fmaf(0.3275911f, ax, 1.f));
    float pl = fmaf(fmaf(fmaf(fmaf(1.061405429f, u, -1.453152027f),
                               u, 1.421413741f),
                          u, -0.284496736f),
                     u, 0.254829592f) * u;
    float e_ = ex2a(-1.44269504088896f * (ax * ax));
    float er = fmaf(-pl, e_, 1.f);
    er = copysignf(er, xn);
    s_h2[wid][lane] = 0.5f * xn * (1.f + er);
    __syncwarp();

    if (lane < 16) {
        float o_ = ob2[lane];
#pragma unroll
        for (int k = 0; k < 32; k++) o_ = fmaf(ow2[lane * 32 + k], s_h2[wid][k], o_);
        out[row * 16 + lane] = o_;
    }
}

extern "C" void kernel_launch(void* const* d_in, const int* in_sizes, int n_in,
                              void* d_out, int out_size) {
    const float* params = (const float*)d_in[0];
    const float* iw1  = (const float*)d_in[1];
    const float* ib1  = (const float*)d_in[2];
    const float* ig1  = (const float*)d_in[3];
    const float* ibt1 = (const float*)d_in[4];
    const float* iw2  = (const float*)d_in[5];
    const float* ib2  = (const float*)d_in[6];
    const float* ow1  = (const float*)d_in[7];
    const float* ob1  = (const float*)d_in[8];
    const float* og1  = (const float*)d_in[9];
    const float* obt1 = (const float*)d_in[10];
    const float* ow2  = (const float*)d_in[11];
    const float* ob2  = (const float*)d_in[12];
    float* out = (float*)d_out;

    pre_kernel<<<65, 32>>>(params, iw1, ib1, ig1, ibt1, iw2);
    pair_kernel<<<NBLK, TPB>>>(ib2);
    final_kernel<<<N / 8, TPB>>>(ow1, ob1, og1, obt1, ow2, ob2, out);
}

// round 12
// speedup vs baseline: 3.3035x; 1.2613x over previous
#include <cuda_runtime.h>
#include <math.h>

#define N    2048
#define HID  16
#define TPB  256
#define T    32
#define NT   (N / T)               // 64
#define NBLK (NT * (NT + 1) / 2)   // 2080

// Per-signal derived scalars: [i*2+0]={t,ra,dec,mc}  [i*2+1]={f_isco,dist,psi,0}
__device__ float4 g_pre4[2 * N];
// Accumulators per row: {sum_e, sum_e*f0 .. sum_e*f7}
__device__ float g_acc[N * 9];
// Preprocessed importance-net weights (W1c = W1 - colmean, b1c = b1 - mean(b1)):
// g_wA[h]=W1c[h][0..3], g_wB[h]=W1c[h][4..7], g_pp[h]={g1, bt1, 0.5*w2, b1c}
__device__ float4 g_wA[HID], g_wB[HID], g_pp[HID];
__device__ float g_w2g[HID];   // w2*g1 (folded linear dot)
__device__ float g_cL[1];      // sum_h w2*bt1

__device__ __forceinline__ float rcpa(float x) {
    float r; asm("rcp.approx.f32 %0, %1;" : "=f"(r) : "f"(x)); return r;
}
__device__ __forceinline__ float ex2a(float x) {
    float r; asm("ex2.approx.f32 %0, %1;" : "=f"(r) : "f"(x)); return r;
}
__device__ __forceinline__ float lg2a(float x) {
    float r; asm("lg2.approx.f32 %0, %1;" : "=f"(r) : "f"(x)); return r;
}

// ---------------------------------------------------------------------------
// Pre: per-signal scalars (blocks 0-63), weight prep (block 64), acc zeroing.
// ---------------------------------------------------------------------------
__global__ void pre_kernel(const float* __restrict__ p,
                           const float* __restrict__ iw1, const float* __restrict__ ib1,
                           const float* __restrict__ ig1, const float* __restrict__ ibt1,
                           const float* __restrict__ iw2)
{
    int tid = threadIdx.x;
    int b   = blockIdx.x;
    if (b < 64) {
        int i = b * 32 + tid;
        const float* pi = p + i * 15;
        float m1 = fmaf(pi[0], 95.f, 5.f);
        float m2 = fmaf(pi[1], 95.f, 5.f);
        float mc = ex2a(fmaf(0.6f, lg2a(m1 * m2), -0.2f * lg2a(m1 + m2)));
        g_pre4[i * 2 + 0] = make_float4(pi[5], pi[3], pi[4], mc);
        g_pre4[i * 2 + 1] = make_float4(220.f / (m1 + m2), fmaf(pi[2], 2950.f, 50.f), pi[7], 0.f);
        float* za = g_acc + (size_t)i * 9;
#pragma unroll
        for (int k = 0; k < 9; k++) za[k] = 0.f;
    } else {
        __shared__ float s_col[8];
        __shared__ float s_bm;
        if (tid < 8) {
            float s = 0.f;
#pragma unroll
            for (int h = 0; h < HID; h++) s += iw1[h * 8 + tid];
            s_col[tid] = s * (1.f / HID);
        }
        if (tid == 0) {
            float bm = 0.f, cl = 0.f;
#pragma unroll
            for (int h = 0; h < HID; h++) { bm += ib1[h]; cl += iw2[h] * ibt1[h]; }
            s_bm = bm * (1.f / HID);
            g_cL[0] = cl;
        }
        __syncthreads();
        if (tid < HID) {
            int h = tid;
            g_wA[h] = make_float4(iw1[h*8+0] - s_col[0], iw1[h*8+1] - s_col[1],
                                  iw1[h*8+2] - s_col[2], iw1[h*8+3] - s_col[3]);
            g_wB[h] = make_float4(iw1[h*8+4] - s_col[4], iw1[h*8+5] - s_col[5],
                                  iw1[h*8+6] - s_col[6], iw1[h*8+7] - s_col[7]);
            g_pp[h] = make_float4(ig1[h], ibt1[h], 0.5f * iw2[h], ib1[h] - s_bm);
            g_w2g[h] = iw2[h] * ig1[h];
        }
    }
}

// ---------------------------------------------------------------------------
// Pair kernel: 32x32 tiles, triangular grid. Computes e=exp(logit) per pair,
// accumulates {e, e*f0..e*f7} into BOTH row-i and row-j accumulators.
// Row side: each (row, tile) is owned by exactly ONE warp-m, so a 2-step
// butterfly leaves 8 disjoint group sums in lanes 0-7, staged in smem with
// plain stores (no races); one global atomic per (row,k) after the loop.
// ---------------------------------------------------------------------------
__global__ __launch_bounds__(TPB) void pair_kernel(const float* __restrict__ ib2)
{
    __shared__ float4 s_wA[HID], s_wB[HID], s_pp[HID];
    __shared__ float  s_w2g[HID];
    __shared__ float  s_ipre[7][T];
    __shared__ float  s_jred[8][T][9];
    __shared__ float  s_rowpart[T][9][8];   // [row][k][group]

    const int tid  = threadIdx.x;
    const int lane = tid & 31;
    const int wg   = tid >> 5;

    // Triangular decode: blocks enumerate (ti, tj) with tj >= ti.
    int b = blockIdx.x;
    int ti = (int)((2.f * NT + 1.f - sqrtf((2.f * NT + 1.f) * (2.f * NT + 1.f) - 8.f * (float)b)) * 0.5f);
    if (ti >= NT) ti = NT - 1;
    while (ti > 0 && (ti * NT - ti * (ti - 1) / 2) > b) ti--;
    while (((ti + 1) * NT - (ti + 1) * ti / 2) <= b) ti++;
    const int tj = ti + (b - (ti * NT - ti * (ti - 1) / 2));
    const bool diag = (ti == tj);

    if (tid < HID)            s_wA[tid]        = g_wA[tid];
    else if (tid < 2*HID)     s_wB[tid-HID]    = g_wB[tid-HID];
    else if (tid < 3*HID)     s_pp[tid-2*HID]  = g_pp[tid-2*HID];
    else if (tid < 4*HID)     s_w2g[tid-3*HID] = g_w2g[tid-3*HID];
    else if (tid >= 128 && tid < 160) {
        int r = tid - 128;
        int ii = ti * T + r;
        float4 a = g_pre4[ii * 2 + 0];
        float4 c = g_pre4[ii * 2 + 1];
        s_ipre[0][r] = a.x; s_ipre[1][r] = a.y; s_ipre[2][r] = a.z;
        s_ipre[3][r] = a.w; s_ipre[4][r] = c.x; s_ipre[5][r] = c.y;
        s_ipre[6][r] = c.z;
    }

    const float lg0 = ib2[0] + 0.5f * g_cL[0];

    // j-side scalars in registers for the whole block
    const int j = tj * T + lane;
    const float4 ja = g_pre4[j * 2 + 0];
    const float4 jb = g_pre4[j * 2 + 1];
    const float tj_ = ja.x, raj = ja.y, dej = ja.z, mcj = ja.w;
    const float fij = jb.x, dij = jb.y, psj = jb.z;

    float jacc[9];
#pragma unroll
    for (int k = 0; k < 9; k++) jacc[k] = 0.f;

    __syncthreads();

#pragma unroll
    for (int m = 0; m < 4; m++) {
        const int r = (m << 3) + wg;
        float v[9];
        const bool valid = (!diag) || (j > ti * T + r);
        if (valid) {
            const float ti_ = s_ipre[0][r], rai = s_ipre[1][r], dei = s_ipre[2][r];
            const float mci = s_ipre[3][r], fii = s_ipre[4][r], dii = s_ipre[5][r];
            const float psi = s_ipre[6][r];

            float dra = fabsf(rai - raj);
            float dde = fabsf(dei - dej);
            float f0 = fabsf(ti_ - tj_);
            float ss = fmaxf(fmaf(dra, dra, dde * dde), 1e-30f);
            float f1 = ss * rsqrtf(ss);
            float f2 = rcpa(fmaf(fabsf(mci - mcj), (1.f / 30.f), 1.f));
            float f3 = ex2a(-fabsf(fii - fij) * 0.0144269504f);
            float f4 = fminf(dii, dij) * rcpa(fmaxf(dii, dij));
            float f5 = fabsf(psi - psj);

            float zc[HID];
            float var = 0.f, dot = 0.f;
#pragma unroll
            for (int h = 0; h < HID; h++) {
                float4 wa = s_wA[h];
                float4 wb = s_wB[h];
                float a = s_pp[h].w;               // b1c
                a = fmaf(wa.x, f0, a); a = fmaf(wa.y, f1, a);
                a = fmaf(wa.z, f2, a); a = fmaf(wa.w, f3, a);
                a = fmaf(wb.x, f4, a); a = fmaf(wb.y, f5, a);
                a = fmaf(wb.z, dra, a); a = fmaf(wb.w, dde, a);
                zc[h] = a;
                var = fmaf(a, a, var);
                dot = fmaf(s_w2g[h], a, dot);
            }
            float inv = rsqrtf(fmaf(var, (1.f / HID), 1e-5f));
            float lg = fmaf(0.5f * inv, dot, lg0);
            // erf epilogue: A&S 7.1.25 (3-term) — validated rel_err ~6.3e-7
#pragma unroll
            for (int h = 0; h < HID; h++) {
                float4 pp = s_pp[h];
                float xn = fmaf(zc[h] * inv, pp.x, pp.y);
                float ax = fabsf(xn) * 0.70710678118654752f;
                float u  = rcpa(fmaf(0.47047f, ax, 1.f));
                float pl = fmaf(fmaf(0.7478556f, u, -0.0958798f), u, 0.3480242f) * u;
                float e_ = ex2a(-0.72134752044448f * (xn * xn));   // e^{-ax^2}
                float er = fmaf(-pl, e_, 1.f);
                er = copysignf(er, xn);
                lg = fmaf(pp.z * xn, er, lg);     // 0.5*w2*xn*erf
            }
            float e = ex2a(lg * 1.44269504088896f);

            v[0] = e;
            v[1] = e * f0; v[2] = e * f1; v[3] = e * f2; v[4] = e * f3;
            v[5] = e * f4; v[6] = e * f5; v[7] = e * dra; v[8] = e * dde;
#pragma unroll
            for (int k = 0; k < 9; k++) jacc[k] += v[k];
        } else {
#pragma unroll
            for (int k = 0; k < 9; k++) v[k] = 0.f;
        }
        // Row-side: 2-step butterfly -> lanes 0-7 hold 8 disjoint group sums;
        // plain stores into this row's private smem slot (written exactly once).
#pragma unroll
        for (int k = 0; k < 9; k++) {
            float x = v[k];
            x += __shfl_xor_sync(0xFFFFFFFFu, x, 16);
            x += __shfl_xor_sync(0xFFFFFFFFu, x, 8);
            if (lane < 8) s_rowpart[r][k][lane] = x;
        }
    }

    // Col-side staging
#pragma unroll
    for (int k = 0; k < 9; k++) s_jred[wg][lane][k] = jacc[k];
    __syncthreads();

    // Row-side finish: 288 (r,k) items, strided so ALL are covered.
    for (int it = tid; it < T * 9; it += TPB) {
        int r = it / 9, k = it - r * 9;
        const float* q = s_rowpart[r][k];
        float s = ((q[0] + q[1]) + (q[2] + q[3])) + ((q[4] + q[5]) + (q[6] + q[7]));
        atomicAdd(&g_acc[(size_t)(ti * T + r) * 9 + k], s);
    }
    // Col-side finish: threads 0-31, one column each (single clean path).
    if (tid < T) {
        const int jj = tj * T + tid;
#pragma unroll
        for (int k = 0; k < 9; k++) {
            float s = 0.f;
#pragma unroll
            for (int w = 0; w < 8; w++) s += s_jred[w][tid][k];
            atomicAdd(&g_acc[(size_t)jj * 9 + k], s);
        }
    }
}

// ---------------------------------------------------------------------------
// Final: normalize + overlap net. One warp per row.
// ---------------------------------------------------------------------------
__global__ __launch_bounds__(TPB) void final_kernel(
    const float* __restrict__ ow1, const float* __restrict__ ob1,
    const float* __restrict__ og1, const float* __restrict__ obt1,
    const float* __restrict__ ow2, const float* __restrict__ ob2,
    float* __restrict__ out)
{
    __shared__ float s_h2[8][32];
    const int tid  = threadIdx.x;
    const int lane = tid & 31;
    const int wid  = tid >> 5;
    const int row  = blockIdx.x * 8 + wid;

    float myv = (lane < 9) ? g_acc[(size_t)row * 9 + lane] : 0.f;
    float invS = rcpa(__shfl_sync(0xFFFFFFFFu, myv, 0));

    float a = ob1[lane];
#pragma unroll
    for (int f = 0; f < 8; f++)
        a = fmaf(ow1[lane * 8 + f], __shfl_sync(0xFFFFFFFFu, myv, f + 1) * invS, a);

    float s = a;
#pragma unroll
    for (int o = 16; o; o >>= 1) s += __shfl_xor_sync(0xFFFFFFFFu, s, o);
    float mu = s * (1.f / 32.f);
    float d = a - mu;
    float v = d * d;
#pragma unroll
    for (int o = 16; o; o >>= 1) v += __shfl_xor_sync(0xFFFFFFFFu, v, o);
    float invs = rsqrtf(fmaf(v, (1.f / 32.f), 1e-5f));
    float xn = fmaf(d * invs, og1[lane], obt1[lane]);

    float ax = fabsf(xn) * 0.70710678118654752f;
    float u  = rcpa(fmaf(0.3275911f, ax, 1.f));
    float pl = fmaf(fmaf(fmaf(fmaf(1.061405429f, u, -1.453152027f),
                               u, 1.421413741f),
                          u, -0.284496736f),
                     u, 0.254829592f) * u;
    float e_ = ex2a(-1.44269504088896f * (ax * ax));
    float er = fmaf(-pl, e_, 1.f);
    er = copysignf(er, xn);
    s_h2[wid][lane] = 0.5f * xn * (1.f + er);
    __syncwarp();

    if (lane < 16) {
        float o_ = ob2[lane];
#pragma unroll
        for (int k = 0; k < 32; k++) o_ = fmaf(ow2[lane * 32 + k], s_h2[wid][k], o_);
        out[row * 16 + lane] = o_;
    }
}

extern "C" void kernel_launch(void* const* d_in, const int* in_sizes, int n_in,
                              void* d_out, int out_size) {
    const float* params = (const float*)d_in[0];
    const float* iw1  = (const float*)d_in[1];
    const float* ib1  = (const float*)d_in[2];
    const float* ig1  = (const float*)d_in[3];
    const float* ibt1 = (const float*)d_in[4];
    const float* iw2  = (const float*)d_in[5];
    const float* ib2  = (const float*)d_in[6];
    const float* ow1  = (const float*)d_in[7];
    const float* ob1  = (const float*)d_in[8];
    const float* og1  = (const float*)d_in[9];
    const float* obt1 = (const float*)d_in[10];
    const float* ow2  = (const float*)d_in[11];
    const float* ob2  = (const float*)d_in[12];
    float* out = (float*)d_out;

    pre_kernel<<<65, 32>>>(params, iw1, ib1, ig1, ibt1, iw2);
    pair_kernel<<<NBLK, TPB>>>(ib2);
    final_kernel<<<N / 8, TPB>>>(ow1, ob1, og1, obt1, ow2, ob2, out);
}

// round 13
// speedup vs baseline: 3.8481x; 1.1649x over previous
#include <cuda_runtime.h>
#include <math.h>

#define N    2048
#define HID  16
#define TPB  256
#define T    32
#define NT   (N / T)               // 64
#define NBLK (NT * (NT + 1) / 2)   // 2080

// Per-signal derived scalars: [i*2+0]={t,ra,dec,mc}  [i*2+1]={f_isco,dist,psi,0}
__device__ float4 g_pre4[2 * N];
// Accumulators per row: {sum_e, sum_e*f0 .. sum_e*f7}
__device__ float g_acc[N * 9];
// Preprocessed importance-net weights (W1c = W1 - colmean, b1c = b1 - mean(b1)):
// g_wA[h]=W1c[h][0..3], g_wB[h]=W1c[h][4..7], g_pp[h]={g1, bt1, w2, b1c}
__device__ float4 g_wA[HID], g_wB[HID], g_pp[HID];

__device__ __forceinline__ float rcpa(float x) {
    float r; asm("rcp.approx.f32 %0, %1;" : "=f"(r) : "f"(x)); return r;
}
__device__ __forceinline__ float ex2a(float x) {
    float r; asm("ex2.approx.f32 %0, %1;" : "=f"(r) : "f"(x)); return r;
}
__device__ __forceinline__ float lg2a(float x) {
    float r; asm("lg2.approx.f32 %0, %1;" : "=f"(r) : "f"(x)); return r;
}

// ---------------------------------------------------------------------------
// Pre: per-signal scalars (blocks 0-63), weight prep (block 64), acc zeroing.
// ---------------------------------------------------------------------------
__global__ void pre_kernel(const float* __restrict__ p,
                           const float* __restrict__ iw1, const float* __restrict__ ib1,
                           const float* __restrict__ ig1, const float* __restrict__ ibt1,
                           const float* __restrict__ iw2)
{
    int tid = threadIdx.x;
    int b   = blockIdx.x;
    if (b < 64) {
        int i = b * 32 + tid;
        const float* pi = p + i * 15;
        float m1 = fmaf(pi[0], 95.f, 5.f);
        float m2 = fmaf(pi[1], 95.f, 5.f);
        float mc = ex2a(fmaf(0.6f, lg2a(m1 * m2), -0.2f * lg2a(m1 + m2)));
        g_pre4[i * 2 + 0] = make_float4(pi[5], pi[3], pi[4], mc);
        g_pre4[i * 2 + 1] = make_float4(220.f / (m1 + m2), fmaf(pi[2], 2950.f, 50.f), pi[7], 0.f);
        float* za = g_acc + (size_t)i * 9;
#pragma unroll
        for (int k = 0; k < 9; k++) za[k] = 0.f;
    } else {
        __shared__ float s_col[8];
        __shared__ float s_bm;
        if (tid < 8) {
            float s = 0.f;
#pragma unroll
            for (int h = 0; h < HID; h++) s += iw1[h * 8 + tid];
            s_col[tid] = s * (1.f / HID);
        }
        if (tid == 0) {
            float bm = 0.f;
#pragma unroll
            for (int h = 0; h < HID; h++) bm += ib1[h];
            s_bm = bm * (1.f / HID);
        }
        __syncthreads();
        if (tid < HID) {
            int h = tid;
            g_wA[h] = make_float4(iw1[h*8+0] - s_col[0], iw1[h*8+1] - s_col[1],
                                  iw1[h*8+2] - s_col[2], iw1[h*8+3] - s_col[3]);
            g_wB[h] = make_float4(iw1[h*8+4] - s_col[4], iw1[h*8+5] - s_col[5],
                                  iw1[h*8+6] - s_col[6], iw1[h*8+7] - s_col[7]);
            g_pp[h] = make_float4(ig1[h], ibt1[h], iw2[h], ib1[h] - s_bm);
        }
    }
}

// ---------------------------------------------------------------------------
// Pair kernel: 32x32 tiles, triangular grid. Computes e=exp(logit) per pair,
// accumulates {e, e*f0..e*f7} into BOTH row-i and row-j accumulators.
// Row side: 1-step butterfly (xor16) -> lanes 0-15 hold 16 disjoint group
// sums, staged race-free in smem; one global atomic per (row,k) after loop.
// ---------------------------------------------------------------------------
__global__ __launch_bounds__(TPB) void pair_kernel(const float* __restrict__ ib2)
{
    __shared__ float4 s_wA[HID], s_wB[HID], s_pp[HID];
    __shared__ float  s_ipre[7][T];
    __shared__ float  s_jred[8][T][9];
    __shared__ float  s_row[T][16][9];   // [row][group][k], 18 KB

    const int tid  = threadIdx.x;
    const int lane = tid & 31;
    const int wg   = tid >> 5;

    // Triangular decode: blocks enumerate (ti, tj) with tj >= ti.
    int b = blockIdx.x;
    int ti = (int)((2.f * NT + 1.f - sqrtf((2.f * NT + 1.f) * (2.f * NT + 1.f) - 8.f * (float)b)) * 0.5f);
    if (ti >= NT) ti = NT - 1;
    while (ti > 0 && (ti * NT - ti * (ti - 1) / 2) > b) ti--;
    while (((ti + 1) * NT - (ti + 1) * ti / 2) <= b) ti++;
    const int tj = ti + (b - (ti * NT - ti * (ti - 1) / 2));
    const bool diag = (ti == tj);

    if (tid < HID)            s_wA[tid]        = g_wA[tid];
    else if (tid < 2*HID)     s_wB[tid-HID]    = g_wB[tid-HID];
    else if (tid < 3*HID)     s_pp[tid-2*HID]  = g_pp[tid-2*HID];
    else if (tid >= 128 && tid < 160) {
        int r = tid - 128;
        int ii = ti * T + r;
        float4 a = g_pre4[ii * 2 + 0];
        float4 c = g_pre4[ii * 2 + 1];
        s_ipre[0][r] = a.x; s_ipre[1][r] = a.y; s_ipre[2][r] = a.z;
        s_ipre[3][r] = a.w; s_ipre[4][r] = c.x; s_ipre[5][r] = c.y;
        s_ipre[6][r] = c.z;
    }

    const float lg0 = ib2[0];

    // tanh-GELU constants: gelu(x) = x * sigmoid(1.5957691*(x + 0.044715*x^3))
    // folded with log2e for ex2: arg = xn * (C1 + C2*xn^2), e = 2^arg
    const float C1 = -2.30220822f;    // -2 * 0.7978845608 * log2(e)
    const float C2 = -0.102943243f;   // C1 * 0.044715

    // j-side scalars in registers for the whole block
    const int j = tj * T + lane;
    const float4 ja = g_pre4[j * 2 + 0];
    const float4 jb = g_pre4[j * 2 + 1];
    const float tj_ = ja.x, raj = ja.y, dej = ja.z, mcj = ja.w;
    const float fij = jb.x, dij = jb.y, psj = jb.z;

    float jacc[9];
#pragma unroll
    for (int k = 0; k < 9; k++) jacc[k] = 0.f;

    __syncthreads();

#pragma unroll
    for (int m = 0; m < 4; m++) {
        const int r = (m << 3) + wg;
        float v[9];
        const bool valid = (!diag) || (j > ti * T + r);
        if (valid) {
            const float ti_ = s_ipre[0][r], rai = s_ipre[1][r], dei = s_ipre[2][r];
            const float mci = s_ipre[3][r], fii = s_ipre[4][r], dii = s_ipre[5][r];
            const float psi = s_ipre[6][r];

            float dra = fabsf(rai - raj);
            float dde = fabsf(dei - dej);
            float f0 = fabsf(ti_ - tj_);
            float ss = fmaxf(fmaf(dra, dra, dde * dde), 1e-30f);
            float f1 = ss * rsqrtf(ss);
            float f2 = rcpa(fmaf(fabsf(mci - mcj), (1.f / 30.f), 1.f));
            float f3 = ex2a(-fabsf(fii - fij) * 0.0144269504f);
            float f4 = fminf(dii, dij) * rcpa(fmaxf(dii, dij));
            float f5 = fabsf(psi - psj);

            float zc[HID];
            float var = 0.f;
#pragma unroll
            for (int h = 0; h < HID; h++) {
                float4 wa = s_wA[h];
                float4 wb = s_wB[h];
                float a = s_pp[h].w;               // b1c
                a = fmaf(wa.x, f0, a); a = fmaf(wa.y, f1, a);
                a = fmaf(wa.z, f2, a); a = fmaf(wa.w, f3, a);
                a = fmaf(wb.x, f4, a); a = fmaf(wb.y, f5, a);
                a = fmaf(wb.z, dra, a); a = fmaf(wb.w, dde, a);
                zc[h] = a;
                var = fmaf(a, a, var);
            }
            float inv = rsqrtf(fmaf(var, (1.f / HID), 1e-5f));
            float lg = lg0;
            // tanh-GELU epilogue: lg += w2 * xn * sigmoid(2*0.79788*(xn+0.044715*xn^3))
#pragma unroll
            for (int h = 0; h < HID; h++) {
                float4 pp = s_pp[h];
                float xn = fmaf(zc[h] * inv, pp.x, pp.y);
                float x2 = xn * xn;
                float ga = xn * fmaf(C2, x2, C1);    // -2g*log2(e)
                float sg = rcpa(1.f + ex2a(ga));      // sigmoid
                lg = fmaf(pp.z * xn, sg, lg);         // w2 * gelu
            }
            float e = ex2a(lg * 1.44269504088896f);

            v[0] = e;
            v[1] = e * f0; v[2] = e * f1; v[3] = e * f2; v[4] = e * f3;
            v[5] = e * f4; v[6] = e * f5; v[7] = e * dra; v[8] = e * dde;
#pragma unroll
            for (int k = 0; k < 9; k++) jacc[k] += v[k];
        } else {
#pragma unroll
            for (int k = 0; k < 9; k++) v[k] = 0.f;
        }
        // Row-side: 1-step butterfly -> lanes 0-15 hold 16 disjoint group sums;
        // plain stores into this row's private smem slot (written exactly once).
#pragma unroll
        for (int k = 0; k < 9; k++) {
            float x = v[k] + __shfl_xor_sync(0xFFFFFFFFu, v[k], 16);
            if (lane < 16) s_row[r][lane][k] = x;
        }
    }

    // Col-side staging
#pragma unroll
    for (int k = 0; k < 9; k++) s_jred[wg][lane][k] = jacc[k];
    __syncthreads();

    // Row-side finish: 288 (r,k) items, strided so ALL are covered.
    for (int it = tid; it < T * 9; it += TPB) {
        int r = it / 9, k = it - r * 9;
        float s = 0.f;
#pragma unroll
        for (int g = 0; g < 16; g++) s += s_row[r][g][k];
        atomicAdd(&g_acc[(size_t)(ti * T + r) * 9 + k], s);
    }
    // Col-side finish: threads 0-31, one column each.
    if (tid < T) {
        const int jj = tj * T + tid;
#pragma unroll
        for (int k = 0; k < 9; k++) {
            float s = 0.f;
#pragma unroll
            for (int w = 0; w < 8; w++) s += s_jred[w][tid][k];
            atomicAdd(&g_acc[(size_t)jj * 9 + k], s);
        }
    }
}

// ---------------------------------------------------------------------------
// Final: normalize + overlap net. One warp per row.
// ---------------------------------------------------------------------------
__global__ __launch_bounds__(TPB) void final_kernel(
    const float* __restrict__ ow1, const float* __restrict__ ob1,
    const float* __restrict__ og1, const float* __restrict__ obt1,
    const float* __restrict__ ow2, const float* __restrict__ ob2,
    float* __restrict__ out)
{
    __shared__ float s_h2[8][32];
    const int tid  = threadIdx.x;
    const int lane = tid & 31;
    const int wid  = tid >> 5;
    const int row  = blockIdx.x * 8 + wid;

    float myv = (lane < 9) ? g_acc[(size_t)row * 9 + lane] : 0.f;
    float invS = rcpa(__shfl_sync(0xFFFFFFFFu, myv, 0));

    float a = ob1[lane];
#pragma unroll
    for (int f = 0; f < 8; f++)
        a = fmaf(ow1[lane * 8 + f], __shfl_sync(0xFFFFFFFFu, myv, f + 1) * invS, a);

    float s = a;
#pragma unroll
    for (int o = 16; o; o >>= 1) s += __shfl_xor_sync(0xFFFFFFFFu, s, o);
    float mu = s * (1.f / 32.f);
    float d = a - mu;
    float v = d * d;
#pragma unroll
    for (int o = 16; o; o >>= 1) v += __shfl_xor_sync(0xFFFFFFFFu, v, o);
    float invs = rsqrtf(fmaf(v, (1.f / 32.f), 1e-5f));
    float xn = fmaf(d * invs, og1[lane], obt1[lane]);

    // accurate 4-term erf GELU here (only 32 lanes/row — cost irrelevant,
    // keeps the final nonlinearity at full accuracy)
    float ax = fabsf(xn) * 0.70710678118654752f;
    float u  = rcpa(fmaf(0.3275911f, ax, 1.f));
    float pl = fmaf(fmaf(fmaf(fmaf(1.061405429f, u, -1.453152027f),
                               u, 1.421413741f),
                          u, -0.284496736f),
                     u, 0.254829592f) * u;
    float e_ = ex2a(-1.44269504088896f * (ax * ax));
    float er = fmaf(-pl, e_, 1.f);
    er = copysignf(er, xn);
    s_h2[wid][lane] = 0.5f * xn * (1.f + er);
    __syncwarp();

    if (lane < 16) {
        float o_ = ob2[lane];
#pragma unroll
        for (int k = 0; k < 32; k++) o_ = fmaf(ow2[lane * 32 + k], s_h2[wid][k], o_);
        out[row * 16 + lane] = o_;
    }
}

extern "C" void kernel_launch(void* const* d_in, const int* in_sizes, int n_in,
                              void* d_out, int out_size) {
    const float* params = (const float*)d_in[0];
    const float* iw1  = (const float*)d_in[1];
    const float* ib1  = (const float*)d_in[2];
    const float* ig1  = (const float*)d_in[3];
    const float* ibt1 = (const float*)d_in[4];
    const float* iw2  = (const float*)d_in[5];
    const float* ib2  = (const float*)d_in[6];
    const float* ow1  = (const float*)d_in[7];
    const float* ob1  = (const float*)d_in[8];
    const float* og1  = (const float*)d_in[9];
    const float* obt1 = (const float*)d_in[10];
    const float* ow2  = (const float*)d_in[11];
    const float* ob2  = (const float*)d_in[12];
    float* out = (float*)d_out;

    pre_kernel<<<65, 32>>>(params, iw1, ib1, ig1, ibt1, iw2);
    pair_kernel<<<NBLK, TPB>>>(ib2);
    final_kernel<<<N / 8, TPB>>>(ow1, ob1, og1, obt1, ow2, ob2, out);
}

// round 14
// speedup vs baseline: 5.2034x; 1.3522x over previous
#include <cuda_runtime.h>
#include <cuda_fp16.h>
#include <math.h>

#define N    2048
#define HID  16
#define TPB  256
#define T    32
#define NT   (N / T)               // 64
#define NBLK (NT * (NT + 1) / 2)   // 2080

// Per-signal derived scalars: [i*2+0]={t,ra,dec,mc}  [i*2+1]={f_isco,dist,psi,0}
__device__ float4 g_pre4[2 * N];
// Accumulators per row: {sum_e, sum_e*f0 .. sum_e*f7}
__device__ float g_acc[N * 9];
// Preprocessed importance-net weights (W1c = W1 - colmean, b1c = b1 - mean(b1)):
// g_wh[k*8+hp] = half2( W1c[hp][k], W1c[hp+8][k] )   (GEMV weights, fp16)
// g_bh[hp]     = half2( b1c[hp], b1c[hp+8] )
// g_pp[h]      = { g1[h], bt1[h], 0.5*w2[h], 0 }
__device__ __half2 g_wh[64];
__device__ __half2 g_bh[8];
__device__ float4  g_pp[HID];

__device__ __forceinline__ float rcpa(float x) {
    float r; asm("rcp.approx.f32 %0, %1;" : "=f"(r) : "f"(x)); return r;
}
__device__ __forceinline__ float ex2a(float x) {
    float r; asm("ex2.approx.f32 %0, %1;" : "=f"(r) : "f"(x)); return r;
}
__device__ __forceinline__ float lg2a(float x) {
    float r; asm("lg2.approx.f32 %0, %1;" : "=f"(r) : "f"(x)); return r;
}
__device__ __forceinline__ float tanha(float x) {
    float r; asm("tanh.approx.f32 %0, %1;" : "=f"(r) : "f"(x)); return r;
}
__device__ __forceinline__ __half2 fh2(float f) {
    unsigned u = __float_as_uint(f);
    return *reinterpret_cast<__half2*>(&u);
}

// ---------------------------------------------------------------------------
// Pre: per-signal scalars (blocks 0-63), weight prep (block 64), acc zeroing.
// ---------------------------------------------------------------------------
__global__ void pre_kernel(const float* __restrict__ p,
                           const float* __restrict__ iw1, const float* __restrict__ ib1,
                           const float* __restrict__ ig1, const float* __restrict__ ibt1,
                           const float* __restrict__ iw2)
{
    int tid = threadIdx.x;
    int b   = blockIdx.x;
    if (b < 64) {
        int i = b * 32 + tid;
        const float* pi = p + i * 15;
        float m1 = fmaf(pi[0], 95.f, 5.f);
        float m2 = fmaf(pi[1], 95.f, 5.f);
        float mc = ex2a(fmaf(0.6f, lg2a(m1 * m2), -0.2f * lg2a(m1 + m2)));
        g_pre4[i * 2 + 0] = make_float4(pi[5], pi[3], pi[4], mc);
        g_pre4[i * 2 + 1] = make_float4(220.f / (m1 + m2), fmaf(pi[2], 2950.f, 50.f), pi[7], 0.f);
        float* za = g_acc + (size_t)i * 9;
#pragma unroll
        for (int k = 0; k < 9; k++) za[k] = 0.f;
    } else {
        __shared__ float s_col[8];
        __shared__ float s_bm;
        if (tid < 8) {
            float s = 0.f;
#pragma unroll
            for (int h = 0; h < HID; h++) s += iw1[h * 8 + tid];
            s_col[tid] = s * (1.f / HID);
        }
        if (tid == 0) {
            float bm = 0.f;
#pragma unroll
            for (int h = 0; h < HID; h++) bm += ib1[h];
            s_bm = bm * (1.f / HID);
        }
        __syncthreads();
        for (int t = tid; t < 64; t += 32) {
            int hp = t & 7, k = t >> 3;
            g_wh[t] = __floats2half2_rn(iw1[hp * 8 + k]       - s_col[k],
                                        iw1[(hp + 8) * 8 + k] - s_col[k]);
        }
        if (tid < 8)
            g_bh[tid] = __floats2half2_rn(ib1[tid] - s_bm, ib1[tid + 8] - s_bm);
        if (tid < HID)
            g_pp[tid] = make_float4(ig1[tid], ibt1[tid], 0.5f * iw2[tid], 0.f);
    }
}

// ---------------------------------------------------------------------------
// Pair kernel: 32x32 tiles, triangular grid. Computes e=exp(logit) per pair,
// accumulates {e, e*f0..e*f7} into BOTH row-i and row-j accumulators.
// GEMV in fp16x2 (HFMA2, h paired with h+8); LN + GELU epilogue in fp32.
// Row side: 1-step butterfly (xor16) -> lanes 0-15 hold 16 disjoint group
// sums, staged race-free in smem; one global atomic per (row,k) after loop.
// ---------------------------------------------------------------------------
__global__ __launch_bounds__(TPB) void pair_kernel(const float* __restrict__ ib2)
{
    __shared__ __align__(16) __half2 s_wh[64];
    __shared__ __half2 s_bh[8];
    __shared__ float4  s_pp[HID];
    __shared__ float   s_ipre[7][T];
    __shared__ float   s_jred[8][T][9];
    __shared__ float   s_row[T][16][9];   // [row][group][k], 18 KB

    const int tid  = threadIdx.x;
    const int lane = tid & 31;
    const int wg   = tid >> 5;

    // Triangular decode: blocks enumerate (ti, tj) with tj >= ti.
    int b = blockIdx.x;
    int ti = (int)((2.f * NT + 1.f - sqrtf((2.f * NT + 1.f) * (2.f * NT + 1.f) - 8.f * (float)b)) * 0.5f);
    if (ti >= NT) ti = NT - 1;
    while (ti > 0 && (ti * NT - ti * (ti - 1) / 2) > b) ti--;
    while (((ti + 1) * NT - (ti + 1) * ti / 2) <= b) ti++;
    const int tj = ti + (b - (ti * NT - ti * (ti - 1) / 2));
    const bool diag = (ti == tj);

    if (tid < 64)                      s_wh[tid]        = g_wh[tid];
    else if (tid < 72)                 s_bh[tid - 64]   = g_bh[tid - 64];
    else if (tid >= 80 && tid < 96)    s_pp[tid - 80]   = g_pp[tid - 80];
    else if (tid >= 128 && tid < 160) {
        int r = tid - 128;
        int ii = ti * T + r;
        float4 a = g_pre4[ii * 2 + 0];
        float4 c = g_pre4[ii * 2 + 1];
        s_ipre[0][r] = a.x; s_ipre[1][r] = a.y; s_ipre[2][r] = a.z;
        s_ipre[3][r] = a.w; s_ipre[4][r] = c.x; s_ipre[5][r] = c.y;
        s_ipre[6][r] = c.z;
    }

    const float lg0 = ib2[0];
    const float TA = 0.7978845608f;     // sqrt(2/pi)
    const float TB = 0.035677408f;      // TA * 0.044715

    // j-side scalars in registers for the whole block
    const int j = tj * T + lane;
    const float4 ja = g_pre4[j * 2 + 0];
    const float4 jb = g_pre4[j * 2 + 1];
    const float tj_ = ja.x, raj = ja.y, dej = ja.z, mcj = ja.w;
    const float fij = jb.x, dij = jb.y, psj = jb.z;

    float jacc[9];
#pragma unroll
    for (int k = 0; k < 9; k++) jacc[k] = 0.f;

    __syncthreads();

#pragma unroll
    for (int m = 0; m < 4; m++) {
        const int r = (m << 3) + wg;
        float v[9];
        const bool valid = (!diag) || (j > ti * T + r);
        if (valid) {
            const float ti_ = s_ipre[0][r], rai = s_ipre[1][r], dei = s_ipre[2][r];
            const float mci = s_ipre[3][r], fii = s_ipre[4][r], dii = s_ipre[5][r];
            const float psi = s_ipre[6][r];

            float dra = fabsf(rai - raj);
            float dde = fabsf(dei - dej);
            float f0 = fabsf(ti_ - tj_);
            float ss = fmaxf(fmaf(dra, dra, dde * dde), 1e-30f);
            float f1 = ss * rsqrtf(ss);
            float f2 = rcpa(fmaf(fabsf(mci - mcj), (1.f / 30.f), 1.f));
            float f3 = ex2a(-fabsf(fii - fij) * 0.0144269504f);
            float f4 = fminf(dii, dij) * rcpa(fmaxf(dii, dij));
            float f5 = fabsf(psi - psj);

            // ---- fp16x2 GEMV: acc[hp] = {z[hp], z[hp+8]} ----
            float fk[8] = {f0, f1, f2, f3, f4, f5, dra, dde};
            __half2 acc[8];
#pragma unroll
            for (int hp = 0; hp < 8; hp++) acc[hp] = s_bh[hp];
            const float4* wh4 = reinterpret_cast<const float4*>(s_wh);
#pragma unroll
            for (int k = 0; k < 8; k++) {
                __half2 hf = __float2half2_rn(fk[k]);
                float4 wa = wh4[k * 2 + 0];
                float4 wb = wh4[k * 2 + 1];
                acc[0] = __hfma2(fh2(wa.x), hf, acc[0]);
                acc[1] = __hfma2(fh2(wa.y), hf, acc[1]);
                acc[2] = __hfma2(fh2(wa.z), hf, acc[2]);
                acc[3] = __hfma2(fh2(wa.w), hf, acc[3]);
                acc[4] = __hfma2(fh2(wb.x), hf, acc[4]);
                acc[5] = __hfma2(fh2(wb.y), hf, acc[5]);
                acc[6] = __hfma2(fh2(wb.z), hf, acc[6]);
                acc[7] = __hfma2(fh2(wb.w), hf, acc[7]);
            }
            float zc[HID];
            float var = 0.f;
#pragma unroll
            for (int hp = 0; hp < 8; hp++) {
                float2 z = __half22float2(acc[hp]);
                zc[hp] = z.x; zc[hp + 8] = z.y;
                var = fmaf(z.x, z.x, var);
                var = fmaf(z.y, z.y, var);
            }
            float inv = rsqrtf(fmaf(var, (1.f / HID), 1e-5f));
            float lg = lg0;
            // tanh-GELU epilogue (MUFU.TANH): gelu = 0.5*xn*(1+tanh(TA*xn+TB*xn^3))
#pragma unroll
            for (int h = 0; h < HID; h++) {
                float4 pp = s_pp[h];
                float xn = fmaf(zc[h] * inv, pp.x, pp.y);
                float x2 = xn * xn;
                float g  = xn * fmaf(TB, x2, TA);
                float th = tanha(g);
                float hw = pp.z * xn;                 // 0.5*w2*xn
                lg = fmaf(hw, 1.f + th, lg);
            }
            float e = ex2a(lg * 1.44269504088896f);

            v[0] = e;
            v[1] = e * f0; v[2] = e * f1; v[3] = e * f2; v[4] = e * f3;
            v[5] = e * f4; v[6] = e * f5; v[7] = e * dra; v[8] = e * dde;
#pragma unroll
            for (int k = 0; k < 9; k++) jacc[k] += v[k];
        } else {
#pragma unroll
            for (int k = 0; k < 9; k++) v[k] = 0.f;
        }
        // Row-side: 1-step butterfly -> lanes 0-15 hold 16 disjoint group sums;
        // plain stores into this row's private smem slot (written exactly once).
#pragma unroll
        for (int k = 0; k < 9; k++) {
            float x = v[k] + __shfl_xor_sync(0xFFFFFFFFu, v[k], 16);
            if (lane < 16) s_row[r][lane][k] = x;
        }
    }

    // Col-side staging
#pragma unroll
    for (int k = 0; k < 9; k++) s_jred[wg][lane][k] = jacc[k];
    __syncthreads();

    // Row-side finish: 288 (r,k) items, strided so ALL are covered.
    for (int it = tid; it < T * 9; it += TPB) {
        int r = it / 9, k = it - r * 9;
        float s = 0.f;
#pragma unroll
        for (int g = 0; g < 16; g++) s += s_row[r][g][k];
        atomicAdd(&g_acc[(size_t)(ti * T + r) * 9 + k], s);
    }
    // Col-side finish: threads 0-31, one column each.
    if (tid < T) {
        const int jj = tj * T + tid;
#pragma unroll
        for (int k = 0; k < 9; k++) {
            float s = 0.f;
#pragma unroll
            for (int w = 0; w < 8; w++) s += s_jred[w][tid][k];
            atomicAdd(&g_acc[(size_t)jj * 9 + k], s);
        }
    }
}

// ---------------------------------------------------------------------------
// Final: normalize + overlap net. One warp per row.
// ---------------------------------------------------------------------------
__global__ __launch_bounds__(TPB) void final_kernel(
    const float* __restrict__ ow1, const float* __restrict__ ob1,
    const float* __restrict__ og1, const float* __restrict__ obt1,
    const float* __restrict__ ow2, const float* __restrict__ ob2,
    float* __restrict__ out)
{
    __shared__ float s_h2[8][32];
    const int tid  = threadIdx.x;
    const int lane = tid & 31;
    const int wid  = tid >> 5;
    const int row  = blockIdx.x * 8 + wid;

    float myv = (lane < 9) ? g_acc[(size_t)row * 9 + lane] : 0.f;
    float invS = rcpa(__shfl_sync(0xFFFFFFFFu, myv, 0));

    float a = ob1[lane];
#pragma unroll
    for (int f = 0; f < 8; f++)
        a = fmaf(ow1[lane * 8 + f], __shfl_sync(0xFFFFFFFFu, myv, f + 1) * invS, a);

    float s = a;
#pragma unroll
    for (int o = 16; o; o >>= 1) s += __shfl_xor_sync(0xFFFFFFFFu, s, o);
    float mu = s * (1.f / 32.f);
    float d = a - mu;
    float v = d * d;
#pragma unroll
    for (int o = 16; o; o >>= 1) v += __shfl_xor_sync(0xFFFFFFFFu, v, o);
    float invs = rsqrtf(fmaf(v, (1.f / 32.f), 1e-5f));
    float xn = fmaf(d * invs, og1[lane], obt1[lane]);

    // accurate 4-term erf GELU here (only 32 lanes/row — cost irrelevant)
    float ax = fabsf(xn) * 0.70710678118654752f;
    float u  = rcpa(fmaf(0.3275911f, ax, 1.f));
    float pl = fmaf(fmaf(fmaf(fmaf(1.061405429f, u, -1.453152027f),
                               u, 1.421413741f),
                          u, -0.284496736f),
                     u, 0.254829592f) * u;
    float e_ = ex2a(-1.44269504088896f * (ax * ax));
    float er = fmaf(-pl, e_, 1.f);
    er = copysignf(er, xn);
    s_h2[wid][lane] = 0.5f * xn * (1.f + er);
    __syncwarp();

    if (lane < 16) {
        float o_ = ob2[lane];
#pragma unroll
        for (int k = 0; k < 32; k++) o_ = fmaf(ow2[lane * 32 + k], s_h2[wid][k], o_);
        out[row * 16 + lane] = o_;
    }
}

extern "C" void kernel_launch(void* const* d_in, const int* in_sizes, int n_in,
                              void* d_out, int out_size) {
    const float* params = (const float*)d_in[0];
    const float* iw1  = (const float*)d_in[1];
    const float* ib1  = (const float*)d_in[2];
    const float* ig1  = (const float*)d_in[3];
    const float* ibt1 = (const float*)d_in[4];
    const float* iw2  = (const float*)d_in[5];
    const float* ib2  = (const float*)d_in[6];
    const float* ow1  = (const float*)d_in[7];
    const float* ob1  = (const float*)d_in[8];
    const float* og1  = (const float*)d_in[9];
    const float* obt1 = (const float*)d_in[10];
    const float* ow2  = (const float*)d_in[11];
    const float* ob2  = (const float*)d_in[12];
    float* out = (float*)d_out;

    pre_kernel<<<65, 32>>>(params, iw1, ib1, ig1, ibt1, iw2);
    pair_kernel<<<NBLK, TPB>>>(ib2);
    final_kernel<<<N / 8, TPB>>>(ow1, ob1, og1, obt1, ow2, ob2, out);
}

// round 15
// speedup vs baseline: 5.6970x; 1.0949x over previous
#include <cuda_runtime.h>
#include <cuda_fp16.h>
#include <math.h>

#define N    2048
#define HID  16
#define TPB  256
#define T    32
#define NT   (N / T)               // 64
#define NBLK (NT * (NT + 1) / 2)   // 2080

// Per-signal derived scalars: [i*2+0]={t,ra,dec,mc}  [i*2+1]={f_isco,dist,psi,0}
__device__ float4 g_pre4[2 * N];
// Accumulators per row: {sum_e, sum_e*f0 .. sum_e*f7}
__device__ float g_acc[N * 9];
// Preprocessed importance-net weights (W1c = W1 - colmean, b1c = b1 - mean(b1)):
// g_wh[k*8+hp] = half2( W1c[hp][k], W1c[hp+8][k] )   (GEMV weights, fp16)
// g_bh[hp]     = half2( b1c[hp], b1c[hp+8] )
// g_g2/g_bt2   = packed LN gain/bias; g_w2h = packed 0.5*w2
__device__ __half2 g_wh[64];
__device__ __half2 g_bh[8], g_g2[8], g_bt2[8], g_w2h[8];

__device__ __forceinline__ float rcpa(float x) {
    float r; asm("rcp.approx.f32 %0, %1;" : "=f"(r) : "f"(x)); return r;
}
__device__ __forceinline__ float ex2a(float x) {
    float r; asm("ex2.approx.f32 %0, %1;" : "=f"(r) : "f"(x)); return r;
}
__device__ __forceinline__ float lg2a(float x) {
    float r; asm("lg2.approx.f32 %0, %1;" : "=f"(r) : "f"(x)); return r;
}
__device__ __forceinline__ __half2 tanh2a(__half2 x) {
    unsigned xi = *reinterpret_cast<unsigned*>(&x), ri;
    asm("tanh.approx.f16x2 %0, %1;" : "=r"(ri) : "r"(xi));
    return *reinterpret_cast<__half2*>(&ri);
}
__device__ __forceinline__ __half2 fh2(float f) {
    unsigned u = __float_as_uint(f);
    return *reinterpret_cast<__half2*>(&u);
}

// ---------------------------------------------------------------------------
// Pre: per-signal scalars (blocks 0-63), weight prep (block 64), acc zeroing.
// ---------------------------------------------------------------------------
__global__ void pre_kernel(const float* __restrict__ p,
                           const float* __restrict__ iw1, const float* __restrict__ ib1,
                           const float* __restrict__ ig1, const float* __restrict__ ibt1,
                           const float* __restrict__ iw2)
{
    int tid = threadIdx.x;
    int b   = blockIdx.x;
    if (b < 64) {
        int i = b * 32 + tid;
        const float* pi = p + i * 15;
        float m1 = fmaf(pi[0], 95.f, 5.f);
        float m2 = fmaf(pi[1], 95.f, 5.f);
        float mc = ex2a(fmaf(0.6f, lg2a(m1 * m2), -0.2f * lg2a(m1 + m2)));
        g_pre4[i * 2 + 0] = make_float4(pi[5], pi[3], pi[4], mc);
        g_pre4[i * 2 + 1] = make_float4(220.f / (m1 + m2), fmaf(pi[2], 2950.f, 50.f), pi[7], 0.f);
        float* za = g_acc + (size_t)i * 9;
#pragma unroll
        for (int k = 0; k < 9; k++) za[k] = 0.f;
    } else {
        __shared__ float s_col[8];
        __shared__ float s_bm;
        if (tid < 8) {
            float s = 0.f;
#pragma unroll
            for (int h = 0; h < HID; h++) s += iw1[h * 8 + tid];
            s_col[tid] = s * (1.f / HID);
        }
        if (tid == 0) {
            float bm = 0.f;
#pragma unroll
            for (int h = 0; h < HID; h++) bm += ib1[h];
            s_bm = bm * (1.f / HID);
        }
        __syncthreads();
        for (int t = tid; t < 64; t += 32) {
            int hp = t & 7, k = t >> 3;
            g_wh[t] = __floats2half2_rn(iw1[hp * 8 + k]       - s_col[k],
                                        iw1[(hp + 8) * 8 + k] - s_col[k]);
        }
        if (tid < 8) {
            g_bh[tid]  = __floats2half2_rn(ib1[tid] - s_bm, ib1[tid + 8] - s_bm);
            g_g2[tid]  = __floats2half2_rn(ig1[tid], ig1[tid + 8]);
            g_bt2[tid] = __floats2half2_rn(ibt1[tid], ibt1[tid + 8]);
            g_w2h[tid] = __floats2half2_rn(0.5f * iw2[tid], 0.5f * iw2[tid + 8]);
        }
    }
}

// ---------------------------------------------------------------------------
// Pair kernel: 32x32 tiles, triangular grid. Computes e=exp(logit) per pair,
// accumulates {e, e*f0..e*f7} into BOTH row-i and row-j accumulators.
// GEMV AND LN/GELU epilogue in fp16x2 (HFMA2 + MUFU.TANH.f16x2).
// ---------------------------------------------------------------------------
__global__ __launch_bounds__(TPB) void pair_kernel(const float* __restrict__ ib2)
{
    __shared__ __align__(16) __half2 s_wh[64];
    __shared__ __half2 s_bh[8], s_g2[8], s_bt2[8], s_w2h[8];
    __shared__ float   s_ipre[7][T];
    __shared__ float   s_jred[8][T][9];
    __shared__ float   s_row[T][16][9];   // [row][group][k], 18 KB

    const int tid  = threadIdx.x;
    const int lane = tid & 31;
    const int wg   = tid >> 5;

    int b = blockIdx.x;
    int ti = (int)((2.f * NT + 1.f - sqrtf((2.f * NT + 1.f) * (2.f * NT + 1.f) - 8.f * (float)b)) * 0.5f);
    if (ti >= NT) ti = NT - 1;
    while (ti > 0 && (ti * NT - ti * (ti - 1) / 2) > b) ti--;
    while (((ti + 1) * NT - (ti + 1) * ti / 2) <= b) ti++;
    const int tj = ti + (b - (ti * NT - ti * (ti - 1) / 2));
    const bool diag = (ti == tj);

    if (tid < 64) s_wh[tid] = g_wh[tid];
    else if (tid < 72)  s_bh[tid - 64]  = g_bh[tid - 64];
    else if (tid < 80)  s_g2[tid - 72]  = g_g2[tid - 72];
    else if (tid < 88)  s_bt2[tid - 80] = g_bt2[tid - 80];
    else if (tid < 96)  s_w2h[tid - 88] = g_w2h[tid - 88];
    else if (tid >= 128 && tid < 160) {
        int r = tid - 128;
        int ii = ti * T + r;
        float4 a = g_pre4[ii * 2 + 0];
        float4 c = g_pre4[ii * 2 + 1];
        s_ipre[0][r] = a.x; s_ipre[1][r] = a.y; s_ipre[2][r] = a.z;
        s_ipre[3][r] = a.w; s_ipre[4][r] = c.x; s_ipre[5][r] = c.y;
        s_ipre[6][r] = c.z;
    }

    const float lg0 = ib2[0];
    const __half2 TA2  = __float2half2_rn(0.7978845608f);
    const __half2 TB2  = __float2half2_rn(0.035677408f);
    const __half2 ONE2 = __float2half2_rn(1.f);

    const int j = tj * T + lane;
    const float4 ja = g_pre4[j * 2 + 0];
    const float4 jb = g_pre4[j * 2 + 1];
    const float tj_ = ja.x, raj = ja.y, dej = ja.z, mcj = ja.w;
    const float fij = jb.x, dij = jb.y, psj = jb.z;

    float jacc[9];
#pragma unroll
    for (int k = 0; k < 9; k++) jacc[k] = 0.f;

    __syncthreads();

#pragma unroll
    for (int m = 0; m < 4; m++) {
        const int r = (m << 3) + wg;
        float v[9];
        const bool valid = (!diag) || (j > ti * T + r);
        if (valid) {
            const float ti_ = s_ipre[0][r], rai = s_ipre[1][r], dei = s_ipre[2][r];
            const float mci = s_ipre[3][r], fii = s_ipre[4][r], dii = s_ipre[5][r];
            const float psi = s_ipre[6][r];

            float dra = fabsf(rai - raj);
            float dde = fabsf(dei - dej);
            float f0 = fabsf(ti_ - tj_);
            float ss = fmaxf(fmaf(dra, dra, dde * dde), 1e-30f);
            float f1 = ss * rsqrtf(ss);
            float f2 = rcpa(fmaf(fabsf(mci - mcj), (1.f / 30.f), 1.f));
            float f3 = ex2a(-fabsf(fii - fij) * 0.0144269504f);
            float f4 = fminf(dii, dij) * rcpa(fmaxf(dii, dij));
            float f5 = fabsf(psi - psj);

            float fk[8] = {f0, f1, f2, f3, f4, f5, dra, dde};
            __half2 acc[8];
#pragma unroll
            for (int hp = 0; hp < 8; hp++) acc[hp] = s_bh[hp];
            const float4* wh4 = reinterpret_cast<const float4*>(s_wh);
#pragma unroll
            for (int k = 0; k < 8; k++) {
                __half2 hf = __float2half2_rn(fk[k]);
                float4 wa = wh4[k * 2 + 0];
                float4 wb = wh4[k * 2 + 1];
                acc[0] = __hfma2(fh2(wa.x), hf, acc[0]);
                acc[1] = __hfma2(fh2(wa.y), hf, acc[1]);
                acc[2] = __hfma2(fh2(wa.z), hf, acc[2]);
                acc[3] = __hfma2(fh2(wa.w), hf, acc[3]);
                acc[4] = __hfma2(fh2(wb.x), hf, acc[4]);
                acc[5] = __hfma2(fh2(wb.y), hf, acc[5]);
                acc[6] = __hfma2(fh2(wb.z), hf, acc[6]);
                acc[7] = __hfma2(fh2(wb.w), hf, acc[7]);
            }
            __half2 var2 = __float2half2_rn(0.f);
#pragma unroll
            for (int hp = 0; hp < 8; hp++) var2 = __hfma2(acc[hp], acc[hp], var2);
            float2 vf = __half22float2(var2);
            float inv = rsqrtf(fmaf(vf.x + vf.y, (1.f / HID), 1e-5f));
            __half2 inv2 = __float2half2_rn(inv);

            __half2 lg2 = __float2half2_rn(0.f);
#pragma unroll
            for (int hp = 0; hp < 8; hp++) {
                __half2 xn = __hfma2(__hmul2(acc[hp], inv2), s_g2[hp], s_bt2[hp]);
                __half2 x2 = __hmul2(xn, xn);
                __half2 ar = __hmul2(xn, __hfma2(TB2, x2, TA2));
                __half2 th = tanh2a(ar);
                __half2 hw = __hmul2(s_w2h[hp], xn);
                lg2 = __hfma2(hw, __hadd2(ONE2, th), lg2);
            }
            float2 lf = __half22float2(lg2);
            float lg = lg0 + lf.x + lf.y;
            float e = ex2a(lg * 1.44269504088896f);

            v[0] = e;
            v[1] = e * f0; v[2] = e * f1; v[3] = e * f2; v[4] = e * f3;
            v[5] = e * f4; v[6] = e * f5; v[7] = e * dra; v[8] = e * dde;
#pragma unroll
            for (int k = 0; k < 9; k++) jacc[k] += v[k];
        } else {
#pragma unroll
            for (int k = 0; k < 9; k++) v[k] = 0.f;
        }
#pragma unroll
        for (int k = 0; k < 9; k++) {
            float x = v[k] + __shfl_xor_sync(0xFFFFFFFFu, v[k], 16);
            if (lane < 16) s_row[r][lane][k] = x;
        }
    }

#pragma unroll
    for (int k = 0; k < 9; k++) s_jred[wg][lane][k] = jacc[k];
    __syncthreads();

    for (int it = tid; it < T * 9; it += TPB) {
        int r = it / 9, k = it - r * 9;
        float s = 0.f;
#pragma unroll
        for (int g = 0; g < 16; g++) s += s_row[r][g][k];
        atomicAdd(&g_acc[(size_t)(ti * T + r) * 9 + k], s);
    }
    if (tid < T) {
        const int jj = tj * T + tid;
#pragma unroll
        for (int k = 0; k < 9; k++) {
            float s = 0.f;
#pragma unroll
            for (int w = 0; w < 8; w++) s += s_jred[w][tid][k];
            atomicAdd(&g_acc[(size_t)jj * 9 + k], s);
        }
    }
}

// ---------------------------------------------------------------------------
// Final: normalize + overlap net. One warp per row.
// ---------------------------------------------------------------------------
__global__ __launch_bounds__(TPB) void final_kernel(
    const float* __restrict__ ow1, const float* __restrict__ ob1,
    const float* __restrict__ og1, const float* __restrict__ obt1,
    const float* __restrict__ ow2, const float* __restrict__ ob2,
    float* __restrict__ out)
{
    __shared__ float s_h2[8][32];
    const int tid  = threadIdx.x;
    const int lane = tid & 31;
    const int wid  = tid >> 5;
    const int row  = blockIdx.x * 8 + wid;

    float myv = (lane < 9) ? g_acc[(size_t)row * 9 + lane] : 0.f;
    float invS = rcpa(__shfl_sync(0xFFFFFFFFu, myv, 0));

    float a = ob1[lane];
#pragma unroll
    for (int f = 0; f < 8; f++)
        a = fmaf(ow1[lane * 8 + f], __shfl_sync(0xFFFFFFFFu, myv, f + 1) * invS, a);

    float s = a;
#pragma unroll
    for (int o = 16; o; o >>= 1) s += __shfl_xor_sync(0xFFFFFFFFu, s, o);
    float mu = s * (1.f / 32.f);
    float d = a - mu;
    float v = d * d;
#pragma unroll
    for (int o = 16; o; o >>= 1) v += __shfl_xor_sync(0xFFFFFFFFu, v, o);
    float invs = rsqrtf(fmaf(v, (1.f / 32.f), 1e-5f));
    float xn = fmaf(d * invs, og1[lane], obt1[lane]);

    float ax = fabsf(xn) * 0.70710678118654752f;
    float u  = rcpa(fmaf(0.3275911f, ax, 1.f));
    float pl = fmaf(fmaf(fmaf(fmaf(1.061405429f, u, -1.453152027f),
                               u, 1.421413741f),
                          u, -0.284496736f),
                     u, 0.254829592f) * u;
    float e_ = ex2a(-1.44269504088896f * (ax * ax));
    float er = fmaf(-pl, e_, 1.f);
    er = copysignf(er, xn);
    s_h2[wid][lane] = 0.5f * xn * (1.f + er);
    __syncwarp();

    if (lane < 16) {
        float o_ = ob2[lane];
#pragma unroll
        for (int k = 0; k < 32; k++) o_ = fmaf(ow2[lane * 32 + k], s_h2[wid][k], o_);
        out[row * 16 + lane] = o_;
    }
}

extern "C" void kernel_launch(void* const* d_in, const int* in_sizes, int n_in,
                              void* d_out, int out_size) {
    const float* params = (const float*)d_in[0];
    const float* iw1  = (const float*)d_in[1];
    const float* ib1  = (const float*)d_in[2];
    const float* ig1  = (const float*)d_in[3];
    const float* ibt1 = (const float*)d_in[4];
    const float* iw2  = (const float*)d_in[5];
    const float* ib2  = (const float*)d_in[6];
    const float* ow1  = (const float*)d_in[7];
    const float* ob1  = (const float*)d_in[8];
    const float* og1  = (const float*)d_in[9];
    const float* obt1 = (const float*)d_in[10];
    const float* ow2  = (const float*)d_in[11];
    const float* ob2  = (const float*)d_in[12];
    float* out = (float*)d_out;

    pre_kernel<<<65, 32>>>(params, iw1, ib1, ig1, ibt1, iw2);
    pair_kernel<<<NBLK, TPB>>>(ib2);
    final_kernel<<<N / 8, TPB>>>(ow1, ob1, og1, obt1, ow2, ob2, out);
}